// round 8
// baseline (speedup 1.0000x reference)
#include <cuda_runtime.h>
#include <cuda_bf16.h>
#include <cuda_fp16.h>

#define B_ 2
#define HW_ 8192
#define D_ 512
#define L_ 4096
#define KN_ 32
#define HEADS_ 8
#define DH_ 64
#define INNER_ 512
#define MQ (B_ * HW_)   /* 16384 */
#define MC (B_ * L_)    /* 8192  */

// ---------------- device-global scratch (no cudaMalloc allowed) -------------
__device__ __half g_q16[MQ * INNER_];          // fp16 q
__device__ __half g_kv16[MC * 2 * INNER_];     // fp16 kv
__device__ __nv_bfloat16 g_x_hi[MQ * D_],           g_x_lo[MQ * D_];
__device__ __nv_bfloat16 g_c_hi[MC * D_],           g_c_lo[MC * D_];
__device__ __nv_bfloat16 g_wq_hi[D_ * INNER_],      g_wq_lo[D_ * INNER_];
__device__ __nv_bfloat16 g_wkv_hi[D_ * 2 * INNER_], g_wkv_lo[D_ * 2 * INNER_];
__device__ __nv_bfloat16 g_wo_hi[INNER_ * D_],      g_wo_lo[INNER_ * D_];
__device__ __nv_bfloat16 g_at_hi[MQ * INNER_],      g_at_lo[MQ * INNER_];

// ---------------- helpers ----------------------------------------------------
__device__ __forceinline__ void split_pack(float a, float b,
                                           unsigned &whi, unsigned &wlo) {
    __nv_bfloat16 ah = __float2bfloat16(a);
    __nv_bfloat16 bh = __float2bfloat16(b);
    __nv_bfloat16 al = __float2bfloat16(a - __bfloat162float(ah));
    __nv_bfloat16 bl = __float2bfloat16(b - __bfloat162float(bh));
    unsigned short ahu = *(unsigned short*)&ah, bhu = *(unsigned short*)&bh;
    unsigned short alu = *(unsigned short*)&al, blu = *(unsigned short*)&bl;
    whi = ((unsigned)bhu << 16) | ahu;
    wlo = ((unsigned)blu << 16) | alu;
}
__device__ __forceinline__ void ldsm_x4(uint4 &r, unsigned addr) {
    asm volatile("ldmatrix.sync.aligned.m8n8.x4.shared.b16 {%0,%1,%2,%3}, [%4];"
        : "=r"(r.x), "=r"(r.y), "=r"(r.z), "=r"(r.w) : "r"(addr));
}
__device__ __forceinline__ void ldsm_x4_t(uint4 &r, unsigned addr) {
    asm volatile("ldmatrix.sync.aligned.m8n8.x4.trans.shared.b16 {%0,%1,%2,%3}, [%4];"
        : "=r"(r.x), "=r"(r.y), "=r"(r.z), "=r"(r.w) : "r"(addr));
}
// NON-volatile: pure register op; lets ptxas interleave MMAs with LDSM latency.
__device__ __forceinline__ void mma_bf16(float4 &d, const uint4 &a,
                                         unsigned b0, unsigned b1) {
    asm("mma.sync.aligned.m16n8k16.row.col.f32.bf16.bf16.f32 "
        "{%0,%1,%2,%3}, {%4,%5,%6,%7}, {%8,%9}, {%0,%1,%2,%3};"
        : "+f"(d.x), "+f"(d.y), "+f"(d.z), "+f"(d.w)
        : "r"(a.x), "r"(a.y), "r"(a.z), "r"(a.w), "r"(b0), "r"(b1));
}
__device__ __forceinline__ void cp16(unsigned saddr, const void* gaddr) {
    asm volatile("cp.async.cg.shared.global [%0], [%1], 16;"
        :: "r"(saddr), "l"(gaddr));
}

// ---------------- fp32 -> bf16 hi/lo split (memory-bound) -------------------
__global__ __launch_bounds__(256) void split_kernel(
    const float4* __restrict__ src, uint2* __restrict__ hi,
    uint2* __restrict__ lo, int n4)
{
    int i = blockIdx.x * 256 + threadIdx.x;
    if (i >= n4) return;
    float4 v = src[i];
    unsigned h0, l0, h1, l1;
    split_pack(v.x, v.y, h0, l0);
    split_pack(v.z, v.w, h1, l1);
    hi[i] = make_uint2(h0, h1);
    lo[i] = make_uint2(l0, l1);
}

// ---------------------------------------------------------------------------
// Tensor-core GEMM, bf16 hi/lo split inputs. C = A[M,K] @ B[K,N] (+bias).
// Block tile 128x64xK32, 256 threads = 8 warps (4x2 of the verified 32x32
// warp tile), 2 CTAs/SM. All 16 fragment loads hoisted ahead of the 48 MMAs
// per K-tile; MMAs non-volatile so ptxas schedules them under LDSM latency.
// out_half: write C as fp16 (q/kv path) instead of fp32.
// ---------------------------------------------------------------------------
#define AW 20
#define BW2 36
#define A_LO_OFF 10240          /* 128*20 words * 4B */
#define B_HI_OFF 20480
#define B_LO_OFF 25088          /* +32*36*4 */
#define STG_BYTES 29696         /* 2*10240 + 2*4608 */
#define SMEM_BYTES (3 * STG_BYTES)

__global__ __launch_bounds__(256, 2) void gemm_bf16s(
    const __nv_bfloat16* __restrict__ Ah, const __nv_bfloat16* __restrict__ Al,
    const __nv_bfloat16* __restrict__ Bh, const __nv_bfloat16* __restrict__ Bl,
    void* __restrict__ Cv, int M, int N, int K, const float* __restrict__ bias,
    int out_half)
{
    extern __shared__ unsigned sm[];
    const unsigned smbase = (unsigned)__cvta_generic_to_shared(sm);

    const int tid  = threadIdx.x;
    const int lane = tid & 31;
    const int warp = tid >> 5;
    const int wm   = (warp >> 1) * 32;
    const int wn   = (warp & 1) * 32;
    const int blockRow = blockIdx.y * 128;
    const int blockCol = blockIdx.x * 64;

    const int ar = tid >> 1, ac = (tid & 1) * 2;
    const int bk = tid >> 3, bc = tid & 7;
    const __nv_bfloat16* gAh = Ah + (size_t)(blockRow + ar) * K + ac * 8;
    const __nv_bfloat16* gAl = Al + (size_t)(blockRow + ar) * K + ac * 8;
    const __nv_bfloat16* gBh = Bh + (size_t)bk * N + blockCol + bc * 8;
    const __nv_bfloat16* gBl = Bl + (size_t)bk * N + blockCol + bc * 8;
    const unsigned a_sb = ar * 80 + ac * 16;
    const unsigned b_sb = bk * 144 + bc * 16;

    const int a_l_row = lane & 15;
    const int a_l_k   = (lane >> 4) << 2;
    const int b_l_k   = (lane & 7) + ((lane >> 4) << 3);
    const int b_l_n   = ((lane >> 3) & 1) << 2;

    float4 d[2][4];
    #pragma unroll
    for (int i = 0; i < 2; i++)
        #pragma unroll
        for (int j = 0; j < 4; j++) d[i][j] = make_float4(0.f, 0.f, 0.f, 0.f);

    auto issue = [&](int stage, int k0) {
        unsigned s = smbase + stage * STG_BYTES;
        cp16(s + a_sb,                 gAh + k0);
        cp16(s + a_sb + 16,            gAh + k0 + 8);
        cp16(s + A_LO_OFF + a_sb,      gAl + k0);
        cp16(s + A_LO_OFF + a_sb + 16, gAl + k0 + 8);
        cp16(s + B_HI_OFF + b_sb,      gBh + (size_t)k0 * N);
        cp16(s + B_LO_OFF + b_sb,      gBl + (size_t)k0 * N);
    };

    issue(0, 0);
    asm volatile("cp.async.commit_group;" ::: "memory");
    issue(1, 32);
    asm volatile("cp.async.commit_group;" ::: "memory");
    asm volatile("cp.async.wait_group 1;" ::: "memory");
    __syncthreads();

    const int nK = K >> 5;
    for (int i = 0; i < nK; i++) {
        const int stage = i % 3;
        const int kn = (i + 2) << 5;
        if (kn < K) issue((i + 2) % 3, kn);
        asm volatile("cp.async.commit_group;" ::: "memory");

        const unsigned sb = smbase + stage * STG_BYTES;

        // hoist ALL fragment loads (both k16 steps) ahead of the MMA block
        uint4 ah[2][2], al[2][2], bh[2][2], bl[2][2];
        #pragma unroll
        for (int kk = 0; kk < 2; kk++) {
            #pragma unroll
            for (int im = 0; im < 2; im++) {
                unsigned w = ((wm + im * 16 + a_l_row) * AW + kk * 8 + a_l_k) * 4;
                ldsm_x4(ah[kk][im], sb + w);
                ldsm_x4(al[kk][im], sb + A_LO_OFF + w);
            }
            #pragma unroll
            for (int ib = 0; ib < 2; ib++) {
                unsigned w = ((kk * 16 + b_l_k) * BW2 + ((wn + ib * 16) >> 1) + b_l_n) * 4;
                ldsm_x4_t(bh[kk][ib], sb + B_HI_OFF + w);
                ldsm_x4_t(bl[kk][ib], sb + B_LO_OFF + w);
            }
        }
        // per-accumulator order identical to R6: kk0 hh,hl,lh then kk1 hh,hl,lh
        #pragma unroll
        for (int kk = 0; kk < 2; kk++) {
            #pragma unroll
            for (int im = 0; im < 2; im++)
                #pragma unroll
                for (int ib = 0; ib < 2; ib++) {
                    mma_bf16(d[im][ib * 2 + 0], ah[kk][im], bh[kk][ib].x, bh[kk][ib].z);
                    mma_bf16(d[im][ib * 2 + 1], ah[kk][im], bh[kk][ib].y, bh[kk][ib].w);
                }
            #pragma unroll
            for (int im = 0; im < 2; im++)
                #pragma unroll
                for (int ib = 0; ib < 2; ib++) {
                    mma_bf16(d[im][ib * 2 + 0], ah[kk][im], bl[kk][ib].x, bl[kk][ib].z);
                    mma_bf16(d[im][ib * 2 + 1], ah[kk][im], bl[kk][ib].y, bl[kk][ib].w);
                }
            #pragma unroll
            for (int im = 0; im < 2; im++)
                #pragma unroll
                for (int ib = 0; ib < 2; ib++) {
                    mma_bf16(d[im][ib * 2 + 0], al[kk][im], bh[kk][ib].x, bh[kk][ib].z);
                    mma_bf16(d[im][ib * 2 + 1], al[kk][im], bh[kk][ib].y, bh[kk][ib].w);
                }
        }
        asm volatile("cp.async.wait_group 1;" ::: "memory");
        __syncthreads();
    }

    // epilogue
    const int g  = lane >> 2;
    const int t2 = (lane & 3) << 1;
    #pragma unroll
    for (int im = 0; im < 2; im++) {
        const int row0 = blockRow + wm + im * 16 + g;
        #pragma unroll
        for (int j = 0; j < 4; j++) {
            const int col = blockCol + wn + j * 8 + t2;
            float4 v = d[im][j];
            if (bias != nullptr) {
                float b0 = bias[col], b1 = bias[col + 1];
                v.x += b0; v.y += b1; v.z += b0; v.w += b1;
            }
            if (!out_half) {
                float* C = (float*)Cv;
                *(float2*)&C[(size_t)row0 * N + col]       = make_float2(v.x, v.y);
                *(float2*)&C[(size_t)(row0 + 8) * N + col] = make_float2(v.z, v.w);
            } else {
                __half* C = (__half*)Cv;
                *(__half2*)&C[(size_t)row0 * N + col]       = __floats2half2_rn(v.x, v.y);
                *(__half2*)&C[(size_t)(row0 + 8) * N + col] = __floats2half2_rn(v.z, v.w);
            }
        }
    }
}

// ---------------------------------------------------------------------------
// Sparse neighbor attention, fp16 Q and KV.
// ---------------------------------------------------------------------------
__global__ __launch_bounds__(256) void attn_kernel(
    const int* __restrict__ idx, const float* __restrict__ bias)
{
    const int bq   = blockIdx.x;
    const int b    = bq >> 13;
    const int h    = threadIdx.x >> 5;
    const int lane = threadIdx.x & 31;

    __shared__ float qs[INNER_];
    const __half* qsrc = g_q16 + (size_t)bq * INNER_;
    #pragma unroll
    for (int i = threadIdx.x; i < INNER_; i += 256)
        qs[i] = __half2float(qsrc[i]);
    __syncthreads();

    const int   row = b * L_ + (idx[(size_t)bq * KN_ + lane] & (L_ - 1));
    const float bj  = bias[(size_t)bq * KN_ + lane];

    const uint4* kp = (const uint4*)(g_kv16 + (size_t)row * (2 * INNER_) + h * DH_);
    float sim = 0.f;
    #pragma unroll
    for (int t = 0; t < 8; t++) {
        uint4 u = kp[t];
        float2 f0 = __half22float2(*(__half2*)&u.x);
        float2 f1 = __half22float2(*(__half2*)&u.y);
        float2 f2 = __half22float2(*(__half2*)&u.z);
        float2 f3 = __half22float2(*(__half2*)&u.w);
        const float* q8 = qs + h * DH_ + t * 8;
        sim = fmaf(q8[0], f0.x, sim); sim = fmaf(q8[1], f0.y, sim);
        sim = fmaf(q8[2], f1.x, sim); sim = fmaf(q8[3], f1.y, sim);
        sim = fmaf(q8[4], f2.x, sim); sim = fmaf(q8[5], f2.y, sim);
        sim = fmaf(q8[6], f3.x, sim); sim = fmaf(q8[7], f3.y, sim);
    }
    sim = sim * 0.125f + bj;

    float m = sim;
    #pragma unroll
    for (int o = 16; o; o >>= 1) m = fmaxf(m, __shfl_xor_sync(0xffffffffu, m, o));
    float e = __expf(sim - m);
    float s = e;
    #pragma unroll
    for (int o = 16; o; o >>= 1) s += __shfl_xor_sync(0xffffffffu, s, o);
    const float p = e / s;

    float2 acc = make_float2(0.f, 0.f);
    const int off = h * DH_ + lane * 2;
    #pragma unroll
    for (int j = 0; j < KN_; j++) {
        const int   rj = __shfl_sync(0xffffffffu, row, j);
        const float pj = __shfl_sync(0xffffffffu, p, j);
        float2 v2 = __half22float2(
            *(const __half2*)(g_kv16 + (size_t)rj * (2 * INNER_) + INNER_ + off));
        acc.x = fmaf(pj, v2.x, acc.x);
        acc.y = fmaf(pj, v2.y, acc.y);
    }
    unsigned whi, wlo;
    split_pack(acc.x, acc.y, whi, wlo);
    const size_t widx = ((size_t)bq * INNER_ + off) >> 1;
    ((unsigned*)g_at_hi)[widx] = whi;
    ((unsigned*)g_at_lo)[widx] = wlo;
}

// ---------------------------------------------------------------------------
extern "C" void kernel_launch(void* const* d_in, const int* in_sizes, int n_in,
                              void* d_out, int out_size)
{
    const float* x       = (const float*)d_in[0];
    const float* context = (const float*)d_in[1];
    const int*   idx     = (const int*)d_in[2];
    const float* bias    = (const float*)d_in[3];
    const float* Wq      = (const float*)d_in[4];
    const float* Wkv     = (const float*)d_in[5];
    const float* Wo      = (const float*)d_in[6];
    const float* bo      = (const float*)d_in[7];
    float*       out     = (float*)d_out;

    __half *pq16, *pkv16;
    __nv_bfloat16 *xh, *xl, *ch, *cl, *qh, *ql, *kh, *kl, *oh, *ol, *ath, *atl;
    cudaGetSymbolAddress((void**)&pq16,  g_q16);
    cudaGetSymbolAddress((void**)&pkv16, g_kv16);
    cudaGetSymbolAddress((void**)&xh,  g_x_hi);   cudaGetSymbolAddress((void**)&xl,  g_x_lo);
    cudaGetSymbolAddress((void**)&ch,  g_c_hi);   cudaGetSymbolAddress((void**)&cl,  g_c_lo);
    cudaGetSymbolAddress((void**)&qh,  g_wq_hi);  cudaGetSymbolAddress((void**)&ql,  g_wq_lo);
    cudaGetSymbolAddress((void**)&kh,  g_wkv_hi); cudaGetSymbolAddress((void**)&kl,  g_wkv_lo);
    cudaGetSymbolAddress((void**)&oh,  g_wo_hi);  cudaGetSymbolAddress((void**)&ol,  g_wo_lo);
    cudaGetSymbolAddress((void**)&ath, g_at_hi);  cudaGetSymbolAddress((void**)&atl, g_at_lo);

    cudaFuncSetAttribute(gemm_bf16s,
        cudaFuncAttributeMaxDynamicSharedMemorySize, SMEM_BYTES);

    auto splt = [&](const float* s, __nv_bfloat16* h, __nv_bfloat16* l, int n) {
        split_kernel<<<(n / 4 + 255) / 256, 256>>>(
            (const float4*)s, (uint2*)h, (uint2*)l, n / 4);
    };
    splt(x,       xh, xl, MQ * D_);
    splt(context, ch, cl, MC * D_);
    splt(Wq,      qh, ql, D_ * INNER_);
    splt(Wkv,     kh, kl, D_ * 2 * INNER_);
    splt(Wo,      oh, ol, INNER_ * D_);

    // q = x @ Wq (fp16 out)
    gemm_bf16s<<<dim3(INNER_ / 64, MQ / 128), 256, SMEM_BYTES>>>(
        xh, xl, qh, ql, pq16, MQ, INNER_, D_, nullptr, 1);
    // kv = context @ Wkv (fp16 out)
    gemm_bf16s<<<dim3((2 * INNER_) / 64, MC / 128), 256, SMEM_BYTES>>>(
        ch, cl, kh, kl, pkv16, MC, 2 * INNER_, D_, nullptr, 1);
    // sparse attention -> split bf16 attn matrix
    attn_kernel<<<MQ, 256>>>(idx, bias);
    // out = attn @ Wo + bo (fp32 out)
    gemm_bf16s<<<dim3(D_ / 64, MQ / 128), 256, SMEM_BYTES>>>(
        ath, atl, oh, ol, out, MQ, D_, INNER_, bo, 0);
}

// round 9
// speedup vs baseline: 1.5532x; 1.5532x over previous
#include <cuda_runtime.h>
#include <cuda_fp16.h>

#define B_ 2
#define HW_ 8192
#define D_ 512
#define L_ 4096
#define KN_ 32
#define HEADS_ 8
#define DH_ 64
#define INNER_ 512
#define MQ (B_ * HW_)   /* 16384 */
#define MC (B_ * L_)    /* 8192  */

// ---------------- device-global scratch (no cudaMalloc allowed) -------------
__device__ __half g_x16[MQ * D_];
__device__ __half g_c16[MC * D_];
__device__ __half g_wq16[D_ * INNER_];
__device__ __half g_wkv16[D_ * 2 * INNER_];
__device__ __half g_wo16[INNER_ * D_];
__device__ __half g_q16[MQ * INNER_];
__device__ __half g_kv16[MC * 2 * INNER_];
__device__ __half g_at16[MQ * INNER_];

// ---------------- helpers ----------------------------------------------------
__device__ __forceinline__ void ldsm_x4(uint4 &r, unsigned addr) {
    asm volatile("ldmatrix.sync.aligned.m8n8.x4.shared.b16 {%0,%1,%2,%3}, [%4];"
        : "=r"(r.x), "=r"(r.y), "=r"(r.z), "=r"(r.w) : "r"(addr));
}
__device__ __forceinline__ void ldsm_x4_t(uint4 &r, unsigned addr) {
    asm volatile("ldmatrix.sync.aligned.m8n8.x4.trans.shared.b16 {%0,%1,%2,%3}, [%4];"
        : "=r"(r.x), "=r"(r.y), "=r"(r.z), "=r"(r.w) : "r"(addr));
}
__device__ __forceinline__ void mma_f16(float4 &d, const uint4 &a,
                                        unsigned b0, unsigned b1) {
    asm("mma.sync.aligned.m16n8k16.row.col.f32.f16.f16.f32 "
        "{%0,%1,%2,%3}, {%4,%5,%6,%7}, {%8,%9}, {%0,%1,%2,%3};"
        : "+f"(d.x), "+f"(d.y), "+f"(d.z), "+f"(d.w)
        : "r"(a.x), "r"(a.y), "r"(a.z), "r"(a.w), "r"(b0), "r"(b1));
}
__device__ __forceinline__ void cp16(unsigned saddr, const void* gaddr) {
    asm volatile("cp.async.cg.shared.global [%0], [%1], 16;"
        :: "r"(saddr), "l"(gaddr));
}

// ---------------- fp32 -> fp16 convert (memory-bound) -----------------------
__global__ __launch_bounds__(256) void tohalf_kernel(
    const float4* __restrict__ src, uint2* __restrict__ dst, int n4)
{
    int i = blockIdx.x * 256 + threadIdx.x;
    if (i >= n4) return;
    float4 v = src[i];
    __half2 p0 = __floats2half2_rn(v.x, v.y);
    __half2 p1 = __floats2half2_rn(v.z, v.w);
    uint2 o;
    o.x = *(unsigned*)&p0;
    o.y = *(unsigned*)&p1;
    dst[i] = o;
}

// ---------------------------------------------------------------------------
// Single-pass fp16 tensor-core GEMM (fp32 accumulate).
// C[M,N] = A[M,K] @ B[K,N] (+ bias). Block tile 128x64xK32, 256 threads =
// 8 warps (4x2 of the verified 32x32 warp tile), 2 CTAs/SM, 5-stage cp.async.
// A smem [m][k] stride 20 words; B smem [k][n] stride 36 words (padded,
// conflict-free ldmatrix / ldmatrix.trans — layout identical to R6/R7).
// out_half: write C as fp16 (q/kv path) instead of fp32.
// ---------------------------------------------------------------------------
#define AW 20
#define BW2 36
#define B_OFF 10240             /* A = 128*20w*4B = 10240B per stage */
#define STG_BYTES 14848         /* + B 32*36w*4B = 4608B */
#define NSTAGE 5
#define SMEM_BYTES (NSTAGE * STG_BYTES)

__global__ __launch_bounds__(256, 2) void gemm_f16(
    const __half* __restrict__ A, const __half* __restrict__ Bm,
    void* __restrict__ Cv, int M, int N, int K, const float* __restrict__ bias,
    int out_half)
{
    extern __shared__ unsigned sm[];
    const unsigned smbase = (unsigned)__cvta_generic_to_shared(sm);

    const int tid  = threadIdx.x;
    const int lane = tid & 31;
    const int warp = tid >> 5;
    const int wm   = (warp >> 1) * 32;
    const int wn   = (warp & 1) * 32;
    const int blockRow = blockIdx.y * 128;
    const int blockCol = blockIdx.x * 64;

    // loaders: A 128 rows x 4 16B-chunks (2/thread); B 32 rows x 8 (1/thread)
    const int ar = tid >> 1, ac = (tid & 1) * 2;
    const int bk = tid >> 3, bc = tid & 7;
    const __half* gA = A + (size_t)(blockRow + ar) * K + ac * 8;
    const __half* gB = Bm + (size_t)bk * N + blockCol + bc * 8;
    const unsigned a_sb = ar * 80 + ac * 16;
    const unsigned b_sb = bk * 144 + bc * 16;

    // ldmatrix lane maps (verified layout, word offsets)
    const int a_l_row = lane & 15;
    const int a_l_k   = (lane >> 4) << 2;
    const int b_l_k   = (lane & 7) + ((lane >> 4) << 3);
    const int b_l_n   = ((lane >> 3) & 1) << 2;

    float4 d[2][4];
    #pragma unroll
    for (int i = 0; i < 2; i++)
        #pragma unroll
        for (int j = 0; j < 4; j++) d[i][j] = make_float4(0.f, 0.f, 0.f, 0.f);

    auto issue = [&](int stage, int chunk) {
        unsigned s = smbase + stage * STG_BYTES;
        const int k0 = chunk * 32;
        cp16(s + a_sb,          gA + k0);
        cp16(s + a_sb + 16,     gA + k0 + 8);
        cp16(s + B_OFF + b_sb,  gB + (size_t)k0 * N);
    };

    const int nK = K >> 5;     // 16
    #pragma unroll
    for (int c = 0; c < NSTAGE - 1; c++) {
        issue(c, c);
        asm volatile("cp.async.commit_group;" ::: "memory");
    }

    for (int i = 0; i < nK; i++) {
        const int stage = i % NSTAGE;
        asm volatile("cp.async.wait_group %0;" :: "n"(NSTAGE - 2) : "memory");
        __syncthreads();

        const unsigned sb = smbase + stage * STG_BYTES;
        uint4 ah[2][2], bh[2][2];
        #pragma unroll
        for (int kk = 0; kk < 2; kk++) {
            #pragma unroll
            for (int im = 0; im < 2; im++) {
                unsigned w = ((wm + im * 16 + a_l_row) * AW + kk * 8 + a_l_k) * 4;
                ldsm_x4(ah[kk][im], sb + w);
            }
            #pragma unroll
            for (int ib = 0; ib < 2; ib++) {
                unsigned w = ((kk * 16 + b_l_k) * BW2 + ((wn + ib * 16) >> 1) + b_l_n) * 4;
                ldsm_x4_t(bh[kk][ib], sb + B_OFF + w);
            }
        }
        #pragma unroll
        for (int kk = 0; kk < 2; kk++)
            #pragma unroll
            for (int im = 0; im < 2; im++)
                #pragma unroll
                for (int ib = 0; ib < 2; ib++) {
                    mma_f16(d[im][ib * 2 + 0], ah[kk][im], bh[kk][ib].x, bh[kk][ib].z);
                    mma_f16(d[im][ib * 2 + 1], ah[kk][im], bh[kk][ib].y, bh[kk][ib].w);
                }

        if (i + NSTAGE - 1 < nK) issue((i + NSTAGE - 1) % NSTAGE, i + NSTAGE - 1);
        asm volatile("cp.async.commit_group;" ::: "memory");
    }

    // epilogue
    const int g  = lane >> 2;
    const int t2 = (lane & 3) << 1;
    #pragma unroll
    for (int im = 0; im < 2; im++) {
        const int row0 = blockRow + wm + im * 16 + g;
        #pragma unroll
        for (int j = 0; j < 4; j++) {
            const int col = blockCol + wn + j * 8 + t2;
            float4 v = d[im][j];
            if (bias != nullptr) {
                float b0 = bias[col], b1 = bias[col + 1];
                v.x += b0; v.y += b1; v.z += b0; v.w += b1;
            }
            if (!out_half) {
                float* C = (float*)Cv;
                *(float2*)&C[(size_t)row0 * N + col]       = make_float2(v.x, v.y);
                *(float2*)&C[(size_t)(row0 + 8) * N + col] = make_float2(v.z, v.w);
            } else {
                __half* C = (__half*)Cv;
                *(__half2*)&C[(size_t)row0 * N + col]       = __floats2half2_rn(v.x, v.y);
                *(__half2*)&C[(size_t)(row0 + 8) * N + col] = __floats2half2_rn(v.z, v.w);
            }
        }
    }
}

// ---------------------------------------------------------------------------
// Sparse neighbor attention, fp16 Q/KV, fp16 output (single word).
// ---------------------------------------------------------------------------
__global__ __launch_bounds__(256) void attn_kernel(
    const int* __restrict__ idx, const float* __restrict__ bias)
{
    const int bq   = blockIdx.x;
    const int b    = bq >> 13;
    const int h    = threadIdx.x >> 5;
    const int lane = threadIdx.x & 31;

    __shared__ float qs[INNER_];
    const __half* qsrc = g_q16 + (size_t)bq * INNER_;
    #pragma unroll
    for (int i = threadIdx.x; i < INNER_; i += 256)
        qs[i] = __half2float(qsrc[i]);
    __syncthreads();

    const int   row = b * L_ + (idx[(size_t)bq * KN_ + lane] & (L_ - 1));
    const float bj  = bias[(size_t)bq * KN_ + lane];

    const uint4* kp = (const uint4*)(g_kv16 + (size_t)row * (2 * INNER_) + h * DH_);
    float sim = 0.f;
    #pragma unroll
    for (int t = 0; t < 8; t++) {
        uint4 u = kp[t];
        float2 f0 = __half22float2(*(__half2*)&u.x);
        float2 f1 = __half22float2(*(__half2*)&u.y);
        float2 f2 = __half22float2(*(__half2*)&u.z);
        float2 f3 = __half22float2(*(__half2*)&u.w);
        const float* q8 = qs + h * DH_ + t * 8;
        sim = fmaf(q8[0], f0.x, sim); sim = fmaf(q8[1], f0.y, sim);
        sim = fmaf(q8[2], f1.x, sim); sim = fmaf(q8[3], f1.y, sim);
        sim = fmaf(q8[4], f2.x, sim); sim = fmaf(q8[5], f2.y, sim);
        sim = fmaf(q8[6], f3.x, sim); sim = fmaf(q8[7], f3.y, sim);
    }
    sim = sim * 0.125f + bj;

    float m = sim;
    #pragma unroll
    for (int o = 16; o; o >>= 1) m = fmaxf(m, __shfl_xor_sync(0xffffffffu, m, o));
    float e = __expf(sim - m);
    float s = e;
    #pragma unroll
    for (int o = 16; o; o >>= 1) s += __shfl_xor_sync(0xffffffffu, s, o);
    const float p = e / s;

    float2 acc = make_float2(0.f, 0.f);
    const int off = h * DH_ + lane * 2;
    #pragma unroll
    for (int j = 0; j < KN_; j++) {
        const int   rj = __shfl_sync(0xffffffffu, row, j);
        const float pj = __shfl_sync(0xffffffffu, p, j);
        float2 v2 = __half22float2(
            *(const __half2*)(g_kv16 + (size_t)rj * (2 * INNER_) + INNER_ + off));
        acc.x = fmaf(pj, v2.x, acc.x);
        acc.y = fmaf(pj, v2.y, acc.y);
    }
    *(__half2*)(g_at16 + (size_t)bq * INNER_ + off) = __floats2half2_rn(acc.x, acc.y);
}

// ---------------------------------------------------------------------------
extern "C" void kernel_launch(void* const* d_in, const int* in_sizes, int n_in,
                              void* d_out, int out_size)
{
    const float* x       = (const float*)d_in[0];
    const float* context = (const float*)d_in[1];
    const int*   idx     = (const int*)d_in[2];
    const float* bias    = (const float*)d_in[3];
    const float* Wq      = (const float*)d_in[4];
    const float* Wkv     = (const float*)d_in[5];
    const float* Wo      = (const float*)d_in[6];
    const float* bo      = (const float*)d_in[7];
    float*       out     = (float*)d_out;

    __half *x16, *c16, *wq16, *wkv16, *wo16, *q16, *kv16, *at16;
    cudaGetSymbolAddress((void**)&x16,   g_x16);
    cudaGetSymbolAddress((void**)&c16,   g_c16);
    cudaGetSymbolAddress((void**)&wq16,  g_wq16);
    cudaGetSymbolAddress((void**)&wkv16, g_wkv16);
    cudaGetSymbolAddress((void**)&wo16,  g_wo16);
    cudaGetSymbolAddress((void**)&q16,   g_q16);
    cudaGetSymbolAddress((void**)&kv16,  g_kv16);
    cudaGetSymbolAddress((void**)&at16,  g_at16);

    cudaFuncSetAttribute(gemm_f16,
        cudaFuncAttributeMaxDynamicSharedMemorySize, SMEM_BYTES);

    auto cvt = [&](const float* s, __half* d16, int n) {
        tohalf_kernel<<<(n / 4 + 255) / 256, 256>>>(
            (const float4*)s, (uint2*)d16, n / 4);
    };
    cvt(x,       x16,   MQ * D_);
    cvt(context, c16,   MC * D_);
    cvt(Wq,      wq16,  D_ * INNER_);
    cvt(Wkv,     wkv16, D_ * 2 * INNER_);
    cvt(Wo,      wo16,  INNER_ * D_);

    // q = x @ Wq (fp16 out)
    gemm_f16<<<dim3(INNER_ / 64, MQ / 128), 256, SMEM_BYTES>>>(
        x16, wq16, q16, MQ, INNER_, D_, nullptr, 1);
    // kv = context @ Wkv (fp16 out)
    gemm_f16<<<dim3((2 * INNER_) / 64, MC / 128), 256, SMEM_BYTES>>>(
        c16, wkv16, kv16, MC, 2 * INNER_, D_, nullptr, 1);
    // sparse attention -> fp16 attn matrix
    attn_kernel<<<MQ, 256>>>(idx, bias);
    // out = attn @ Wo + bo (fp32 out)
    gemm_f16<<<dim3(D_ / 64, MQ / 128), 256, SMEM_BYTES>>>(
        at16, wo16, out, MQ, D_, INNER_, bo, 0);
}

// round 10
// speedup vs baseline: 1.6525x; 1.0639x over previous
#include <cuda_runtime.h>
#include <cuda_fp16.h>

#define B_ 2
#define HW_ 8192
#define D_ 512
#define L_ 4096
#define KN_ 32
#define HEADS_ 8
#define DH_ 64
#define INNER_ 512
#define MQ (B_ * HW_)   /* 16384 */
#define MC (B_ * L_)    /* 8192  */
#define GK 512          /* K of every GEMM */

// ---------------- device-global scratch (no cudaMalloc allowed) -------------
__device__ __half g_x16[MQ * D_];
__device__ __half g_c16[MC * D_];
__device__ __half g_wq16[D_ * INNER_];
__device__ __half g_wkv16[D_ * 2 * INNER_];
__device__ __half g_wo16[INNER_ * D_];
__device__ __half g_q16[MQ * INNER_];
__device__ __half g_kv16[MC * 2 * INNER_];
__device__ __half g_at16[MQ * INNER_];

// ---------------- helpers ----------------------------------------------------
__device__ __forceinline__ void ldsm_x4(uint4 &r, unsigned addr) {
    asm volatile("ldmatrix.sync.aligned.m8n8.x4.shared.b16 {%0,%1,%2,%3}, [%4];"
        : "=r"(r.x), "=r"(r.y), "=r"(r.z), "=r"(r.w) : "r"(addr));
}
__device__ __forceinline__ void ldsm_x4_t(uint4 &r, unsigned addr) {
    asm volatile("ldmatrix.sync.aligned.m8n8.x4.trans.shared.b16 {%0,%1,%2,%3}, [%4];"
        : "=r"(r.x), "=r"(r.y), "=r"(r.z), "=r"(r.w) : "r"(addr));
}
__device__ __forceinline__ void mma_f16(float4 &d, const uint4 &a,
                                        unsigned b0, unsigned b1) {
    asm("mma.sync.aligned.m16n8k16.row.col.f32.f16.f16.f32 "
        "{%0,%1,%2,%3}, {%4,%5,%6,%7}, {%8,%9}, {%0,%1,%2,%3};"
        : "+f"(d.x), "+f"(d.y), "+f"(d.z), "+f"(d.w)
        : "r"(a.x), "r"(a.y), "r"(a.z), "r"(a.w), "r"(b0), "r"(b1));
}
__device__ __forceinline__ void cp16(unsigned saddr, const void* gaddr) {
    asm volatile("cp.async.cg.shared.global [%0], [%1], 16;"
        :: "r"(saddr), "l"(gaddr));
}

// ---------------- merged fp32 -> fp16 convert (single launch) ---------------
#define CVT_C0 (MQ * D_ / 4)                       /* x    */
#define CVT_C1 (CVT_C0 + MC * D_ / 4)              /* ctx  */
#define CVT_C2 (CVT_C1 + D_ * INNER_ / 4)          /* Wq   */
#define CVT_C3 (CVT_C2 + D_ * 2 * INNER_ / 4)      /* Wkv  */
#define CVT_C4 (CVT_C3 + INNER_ * D_ / 4)          /* Wo   */

__global__ __launch_bounds__(256) void convert_all(
    const float4* __restrict__ x, const float4* __restrict__ c,
    const float4* __restrict__ wq, const float4* __restrict__ wkv,
    const float4* __restrict__ wo)
{
    int i = blockIdx.x * 256 + threadIdx.x;
    if (i >= CVT_C4) return;
    const float4* s; uint2* d; int off;
    if      (i < CVT_C0) { s = x;   d = (uint2*)g_x16;   off = 0; }
    else if (i < CVT_C1) { s = c;   d = (uint2*)g_c16;   off = CVT_C0; }
    else if (i < CVT_C2) { s = wq;  d = (uint2*)g_wq16;  off = CVT_C1; }
    else if (i < CVT_C3) { s = wkv; d = (uint2*)g_wkv16; off = CVT_C2; }
    else                 { s = wo;  d = (uint2*)g_wo16;  off = CVT_C3; }
    const int j = i - off;
    float4 v = s[j];
    __half2 p0 = __floats2half2_rn(v.x, v.y);
    __half2 p1 = __floats2half2_rn(v.z, v.w);
    uint2 o;
    o.x = *(unsigned*)&p0;
    o.y = *(unsigned*)&p1;
    d[j] = o;
}

// ---------------------------------------------------------------------------
// Core fp16 GEMM mainloop (verified R8 layout): block tile 128x64xK32,
// 256 threads = 8 warps (4x2 of 32x32 warp tiles), 2 CTAs/SM, 5-stage
// cp.async. A smem [m][k] stride 20 words; B smem [k][n] stride 36 words.
// Parameterized by ldb (B row stride) and ldc (C row stride).
// ---------------------------------------------------------------------------
#define AW 20
#define BW2 36
#define B_OFF 10240
#define STG_BYTES 14848
#define NSTAGE 5
#define SMEM_BYTES (NSTAGE * STG_BYTES)

template <bool OUT_HALF>
__device__ __forceinline__ void gemm_tile(
    const __half* __restrict__ A,     // 128 rows x K, row stride K
    const __half* __restrict__ Bm,    // K rows, row stride ldb
    void* __restrict__ Cv, int ldb, int ldc,
    const float* __restrict__ bias, int blockCol, unsigned smbase)
{
    const int tid  = threadIdx.x;
    const int lane = tid & 31;
    const int warp = tid >> 5;
    const int wm   = (warp >> 1) * 32;
    const int wn   = (warp & 1) * 32;
    const int K = GK;

    const int ar = tid >> 1, ac = (tid & 1) * 2;
    const int bk = tid >> 3, bc = tid & 7;
    const __half* gA = A + (size_t)ar * K + ac * 8;
    const __half* gB = Bm + (size_t)bk * ldb + blockCol + bc * 8;
    const unsigned a_sb = ar * 80 + ac * 16;
    const unsigned b_sb = bk * 144 + bc * 16;

    const int a_l_row = lane & 15;
    const int a_l_k   = (lane >> 4) << 2;
    const int b_l_k   = (lane & 7) + ((lane >> 4) << 3);
    const int b_l_n   = ((lane >> 3) & 1) << 2;

    float4 d[2][4];
    #pragma unroll
    for (int i = 0; i < 2; i++)
        #pragma unroll
        for (int j = 0; j < 4; j++) d[i][j] = make_float4(0.f, 0.f, 0.f, 0.f);

    auto issue = [&](int stage, int chunk) {
        unsigned s = smbase + stage * STG_BYTES;
        const int k0 = chunk * 32;
        cp16(s + a_sb,          gA + k0);
        cp16(s + a_sb + 16,     gA + k0 + 8);
        cp16(s + B_OFF + b_sb,  gB + (size_t)k0 * ldb);
    };

    const int nK = K >> 5;
    #pragma unroll
    for (int c = 0; c < NSTAGE - 1; c++) {
        issue(c, c);
        asm volatile("cp.async.commit_group;" ::: "memory");
    }

    for (int i = 0; i < nK; i++) {
        const int stage = i % NSTAGE;
        asm volatile("cp.async.wait_group %0;" :: "n"(NSTAGE - 2) : "memory");
        __syncthreads();

        const unsigned sb = smbase + stage * STG_BYTES;
        uint4 ah[2][2], bh[2][2];
        #pragma unroll
        for (int kk = 0; kk < 2; kk++) {
            #pragma unroll
            for (int im = 0; im < 2; im++) {
                unsigned w = ((wm + im * 16 + a_l_row) * AW + kk * 8 + a_l_k) * 4;
                ldsm_x4(ah[kk][im], sb + w);
            }
            #pragma unroll
            for (int ib = 0; ib < 2; ib++) {
                unsigned w = ((kk * 16 + b_l_k) * BW2 + ((wn + ib * 16) >> 1) + b_l_n) * 4;
                ldsm_x4_t(bh[kk][ib], sb + B_OFF + w);
            }
        }
        #pragma unroll
        for (int kk = 0; kk < 2; kk++)
            #pragma unroll
            for (int im = 0; im < 2; im++)
                #pragma unroll
                for (int ib = 0; ib < 2; ib++) {
                    mma_f16(d[im][ib * 2 + 0], ah[kk][im], bh[kk][ib].x, bh[kk][ib].z);
                    mma_f16(d[im][ib * 2 + 1], ah[kk][im], bh[kk][ib].y, bh[kk][ib].w);
                }

        if (i + NSTAGE - 1 < nK) issue((i + NSTAGE - 1) % NSTAGE, i + NSTAGE - 1);
        asm volatile("cp.async.commit_group;" ::: "memory");
    }

    const int g  = lane >> 2;
    const int t2 = (lane & 3) << 1;
    #pragma unroll
    for (int im = 0; im < 2; im++) {
        const int row0 = wm + im * 16 + g;
        #pragma unroll
        for (int j = 0; j < 4; j++) {
            const int col = blockCol + wn + j * 8 + t2;
            float4 v = d[im][j];
            if (bias != nullptr) {
                float b0 = bias[col], b1 = bias[col + 1];
                v.x += b0; v.y += b1; v.z += b0; v.w += b1;
            }
            if (!OUT_HALF) {
                float* C = (float*)Cv;
                *(float2*)&C[(size_t)row0 * ldc + col]       = make_float2(v.x, v.y);
                *(float2*)&C[(size_t)(row0 + 8) * ldc + col] = make_float2(v.z, v.w);
            } else {
                __half* C = (__half*)Cv;
                *(__half2*)&C[(size_t)row0 * ldc + col]       = __floats2half2_rn(v.x, v.y);
                *(__half2*)&C[(size_t)(row0 + 8) * ldc + col] = __floats2half2_rn(v.z, v.w);
            }
        }
    }
}

// Merged q/k/v projection: grid (8, 256). gy<128: q slab; gy<192: k slab
// (Wkv cols 0..511, ldb 1024); else v slab (Wkv cols 512.., C offset +512).
__global__ __launch_bounds__(256, 2) void qkv_gemm()
{
    extern __shared__ unsigned sm[];
    const unsigned smbase = (unsigned)__cvta_generic_to_shared(sm);
    const int gy = blockIdx.y;
    const __half *A, *Bm; __half *C; int ldb, ldc;
    if (gy < 128) {
        A = g_x16 + (size_t)gy * 128 * GK;
        Bm = g_wq16; ldb = 512;
        C = g_q16 + (size_t)gy * 128 * 512; ldc = 512;
    } else if (gy < 192) {
        const int r = gy - 128;
        A = g_c16 + (size_t)r * 128 * GK;
        Bm = g_wkv16; ldb = 1024;
        C = g_kv16 + (size_t)r * 128 * 1024; ldc = 1024;
    } else {
        const int r = gy - 192;
        A = g_c16 + (size_t)r * 128 * GK;
        Bm = g_wkv16 + 512; ldb = 1024;
        C = g_kv16 + (size_t)r * 128 * 1024 + 512; ldc = 1024;
    }
    gemm_tile<true>(A, Bm, C, ldb, ldc, nullptr, blockIdx.x * 64, smbase);
}

// Output projection: out = attn @ Wo + bo (fp32 out).
__global__ __launch_bounds__(256, 2) void out_gemm(
    float* __restrict__ out, const float* __restrict__ bias)
{
    extern __shared__ unsigned sm[];
    const unsigned smbase = (unsigned)__cvta_generic_to_shared(sm);
    const __half* A = g_at16 + (size_t)blockIdx.y * 128 * GK;
    float* C = out + (size_t)blockIdx.y * 128 * 512;
    gemm_tile<false>(A, g_wo16, C, 512, 512, bias, blockIdx.x * 64, smbase);
}

// ---------------------------------------------------------------------------
// Sparse neighbor attention, fp16 Q/KV, fp16 output.
// ---------------------------------------------------------------------------
__global__ __launch_bounds__(256) void attn_kernel(
    const int* __restrict__ idx, const float* __restrict__ bias)
{
    const int bq   = blockIdx.x;
    const int b    = bq >> 13;
    const int h    = threadIdx.x >> 5;
    const int lane = threadIdx.x & 31;

    __shared__ float qs[INNER_];
    const __half2* qsrc = (const __half2*)(g_q16 + (size_t)bq * INNER_);
    #pragma unroll
    for (int i = threadIdx.x; i < INNER_ / 2; i += 256) {
        float2 f = __half22float2(qsrc[i]);
        qs[i * 2] = f.x; qs[i * 2 + 1] = f.y;
    }
    __syncthreads();

    const int   row = b * L_ + (idx[(size_t)bq * KN_ + lane] & (L_ - 1));
    const float bj  = bias[(size_t)bq * KN_ + lane];

    const uint4* kp = (const uint4*)(g_kv16 + (size_t)row * (2 * INNER_) + h * DH_);
    float sim = 0.f;
    #pragma unroll
    for (int t = 0; t < 8; t++) {
        uint4 u = kp[t];
        float2 f0 = __half22float2(*(__half2*)&u.x);
        float2 f1 = __half22float2(*(__half2*)&u.y);
        float2 f2 = __half22float2(*(__half2*)&u.z);
        float2 f3 = __half22float2(*(__half2*)&u.w);
        const float* q8 = qs + h * DH_ + t * 8;
        sim = fmaf(q8[0], f0.x, sim); sim = fmaf(q8[1], f0.y, sim);
        sim = fmaf(q8[2], f1.x, sim); sim = fmaf(q8[3], f1.y, sim);
        sim = fmaf(q8[4], f2.x, sim); sim = fmaf(q8[5], f2.y, sim);
        sim = fmaf(q8[6], f3.x, sim); sim = fmaf(q8[7], f3.y, sim);
    }
    sim = sim * 0.125f + bj;

    float m = sim;
    #pragma unroll
    for (int o = 16; o; o >>= 1) m = fmaxf(m, __shfl_xor_sync(0xffffffffu, m, o));
    float e = __expf(sim - m);
    float s = e;
    #pragma unroll
    for (int o = 16; o; o >>= 1) s += __shfl_xor_sync(0xffffffffu, s, o);
    const float p = e / s;

    float2 acc = make_float2(0.f, 0.f);
    const int off = h * DH_ + lane * 2;
    #pragma unroll
    for (int j = 0; j < KN_; j++) {
        const int   rj = __shfl_sync(0xffffffffu, row, j);
        const float pj = __shfl_sync(0xffffffffu, p, j);
        float2 v2 = __half22float2(
            *(const __half2*)(g_kv16 + (size_t)rj * (2 * INNER_) + INNER_ + off));
        acc.x = fmaf(pj, v2.x, acc.x);
        acc.y = fmaf(pj, v2.y, acc.y);
    }
    *(__half2*)(g_at16 + (size_t)bq * INNER_ + off) = __floats2half2_rn(acc.x, acc.y);
}

// ---------------------------------------------------------------------------
extern "C" void kernel_launch(void* const* d_in, const int* in_sizes, int n_in,
                              void* d_out, int out_size)
{
    const float* x       = (const float*)d_in[0];
    const float* context = (const float*)d_in[1];
    const int*   idx     = (const int*)d_in[2];
    const float* bias    = (const float*)d_in[3];
    const float* Wq      = (const float*)d_in[4];
    const float* Wkv     = (const float*)d_in[5];
    const float* Wo      = (const float*)d_in[6];
    const float* bo      = (const float*)d_in[7];
    float*       out     = (float*)d_out;

    cudaFuncSetAttribute(qkv_gemm,
        cudaFuncAttributeMaxDynamicSharedMemorySize, SMEM_BYTES);
    cudaFuncSetAttribute(out_gemm,
        cudaFuncAttributeMaxDynamicSharedMemorySize, SMEM_BYTES);

    // one launch: convert all fp32 inputs to fp16 scratch
    convert_all<<<(CVT_C4 + 255) / 256, 256>>>(
        (const float4*)x, (const float4*)context,
        (const float4*)Wq, (const float4*)Wkv, (const float4*)Wo);

    // one launch: q, k, v projections (grid.y slabs)
    qkv_gemm<<<dim3(8, 256), 256, SMEM_BYTES>>>();

    // sparse attention -> fp16 attn matrix
    attn_kernel<<<MQ, 256>>>(idx, bias);

    // out = attn @ Wo + bo (fp32 out)
    out_gemm<<<dim3(8, MQ / 128), 256, SMEM_BYTES>>>(out, bo);
}

// round 11
// speedup vs baseline: 1.7127x; 1.0365x over previous
#include <cuda_runtime.h>
#include <cuda_fp16.h>

#define B_ 2
#define HW_ 8192
#define D_ 512
#define L_ 4096
#define KN_ 32
#define HEADS_ 8
#define DH_ 64
#define INNER_ 512
#define MQ (B_ * HW_)   /* 16384 */
#define MC (B_ * L_)    /* 8192  */
#define GK 512          /* K of every GEMM */

// ---------------- device-global scratch (no cudaMalloc allowed) -------------
__device__ __half g_x16[MQ * D_];
__device__ __half g_c16[MC * D_];
__device__ __half g_wq16[D_ * INNER_];
__device__ __half g_wkv16[D_ * 2 * INNER_];
__device__ __half g_wo16[INNER_ * D_];
__device__ __half g_q16[MQ * INNER_];
__device__ __half g_kv16[MC * 2 * INNER_];
__device__ __half g_at16[MQ * INNER_];

// ---------------- helpers ----------------------------------------------------
__device__ __forceinline__ void ldsm_x4(uint4 &r, unsigned addr) {
    asm volatile("ldmatrix.sync.aligned.m8n8.x4.shared.b16 {%0,%1,%2,%3}, [%4];"
        : "=r"(r.x), "=r"(r.y), "=r"(r.z), "=r"(r.w) : "r"(addr));
}
__device__ __forceinline__ void ldsm_x4_t(uint4 &r, unsigned addr) {
    asm volatile("ldmatrix.sync.aligned.m8n8.x4.trans.shared.b16 {%0,%1,%2,%3}, [%4];"
        : "=r"(r.x), "=r"(r.y), "=r"(r.z), "=r"(r.w) : "r"(addr));
}
__device__ __forceinline__ void mma_f16(float4 &d, const uint4 &a,
                                        unsigned b0, unsigned b1) {
    asm("mma.sync.aligned.m16n8k16.row.col.f32.f16.f16.f32 "
        "{%0,%1,%2,%3}, {%4,%5,%6,%7}, {%8,%9}, {%0,%1,%2,%3};"
        : "+f"(d.x), "+f"(d.y), "+f"(d.z), "+f"(d.w)
        : "r"(a.x), "r"(a.y), "r"(a.z), "r"(a.w), "r"(b0), "r"(b1));
}
__device__ __forceinline__ void cp16(unsigned saddr, const void* gaddr) {
    asm volatile("cp.async.cg.shared.global [%0], [%1], 16;"
        :: "r"(saddr), "l"(gaddr));
}

// ---------------- merged fp32 -> fp16 convert (single launch) ---------------
#define CVT_C0 (MQ * D_ / 4)
#define CVT_C1 (CVT_C0 + MC * D_ / 4)
#define CVT_C2 (CVT_C1 + D_ * INNER_ / 4)
#define CVT_C3 (CVT_C2 + D_ * 2 * INNER_ / 4)
#define CVT_C4 (CVT_C3 + INNER_ * D_ / 4)

__global__ __launch_bounds__(256) void convert_all(
    const float4* __restrict__ x, const float4* __restrict__ c,
    const float4* __restrict__ wq, const float4* __restrict__ wkv,
    const float4* __restrict__ wo)
{
    int i = blockIdx.x * 256 + threadIdx.x;
    if (i >= CVT_C4) return;
    const float4* s; uint2* d; int off;
    if      (i < CVT_C0) { s = x;   d = (uint2*)g_x16;   off = 0; }
    else if (i < CVT_C1) { s = c;   d = (uint2*)g_c16;   off = CVT_C0; }
    else if (i < CVT_C2) { s = wq;  d = (uint2*)g_wq16;  off = CVT_C1; }
    else if (i < CVT_C3) { s = wkv; d = (uint2*)g_wkv16; off = CVT_C2; }
    else                 { s = wo;  d = (uint2*)g_wo16;  off = CVT_C3; }
    const int j = i - off;
    float4 v = s[j];
    __half2 p0 = __floats2half2_rn(v.x, v.y);
    __half2 p1 = __floats2half2_rn(v.z, v.w);
    uint2 o;
    o.x = *(unsigned*)&p0;
    o.y = *(unsigned*)&p1;
    d[j] = o;
}

// ---------------------------------------------------------------------------
// Core fp16 GEMM mainloop (verified R8/R9 layout, unchanged).
// ---------------------------------------------------------------------------
#define AW 20
#define BW2 36
#define B_OFF 10240
#define STG_BYTES 14848
#define NSTAGE 5
#define SMEM_BYTES (NSTAGE * STG_BYTES)

template <bool OUT_HALF>
__device__ __forceinline__ void gemm_tile(
    const __half* __restrict__ A, const __half* __restrict__ Bm,
    void* __restrict__ Cv, int ldb, int ldc,
    const float* __restrict__ bias, int blockCol, unsigned smbase)
{
    const int tid  = threadIdx.x;
    const int lane = tid & 31;
    const int warp = tid >> 5;
    const int wm   = (warp >> 1) * 32;
    const int wn   = (warp & 1) * 32;
    const int K = GK;

    const int ar = tid >> 1, ac = (tid & 1) * 2;
    const int bk = tid >> 3, bc = tid & 7;
    const __half* gA = A + (size_t)ar * K + ac * 8;
    const __half* gB = Bm + (size_t)bk * ldb + blockCol + bc * 8;
    const unsigned a_sb = ar * 80 + ac * 16;
    const unsigned b_sb = bk * 144 + bc * 16;

    const int a_l_row = lane & 15;
    const int a_l_k   = (lane >> 4) << 2;
    const int b_l_k   = (lane & 7) + ((lane >> 4) << 3);
    const int b_l_n   = ((lane >> 3) & 1) << 2;

    float4 d[2][4];
    #pragma unroll
    for (int i = 0; i < 2; i++)
        #pragma unroll
        for (int j = 0; j < 4; j++) d[i][j] = make_float4(0.f, 0.f, 0.f, 0.f);

    auto issue = [&](int stage, int chunk) {
        unsigned s = smbase + stage * STG_BYTES;
        const int k0 = chunk * 32;
        cp16(s + a_sb,          gA + k0);
        cp16(s + a_sb + 16,     gA + k0 + 8);
        cp16(s + B_OFF + b_sb,  gB + (size_t)k0 * ldb);
    };

    const int nK = K >> 5;
    #pragma unroll
    for (int c = 0; c < NSTAGE - 1; c++) {
        issue(c, c);
        asm volatile("cp.async.commit_group;" ::: "memory");
    }

    for (int i = 0; i < nK; i++) {
        const int stage = i % NSTAGE;
        asm volatile("cp.async.wait_group %0;" :: "n"(NSTAGE - 2) : "memory");
        __syncthreads();

        const unsigned sb = smbase + stage * STG_BYTES;
        uint4 ah[2][2], bh[2][2];
        #pragma unroll
        for (int kk = 0; kk < 2; kk++) {
            #pragma unroll
            for (int im = 0; im < 2; im++) {
                unsigned w = ((wm + im * 16 + a_l_row) * AW + kk * 8 + a_l_k) * 4;
                ldsm_x4(ah[kk][im], sb + w);
            }
            #pragma unroll
            for (int ib = 0; ib < 2; ib++) {
                unsigned w = ((kk * 16 + b_l_k) * BW2 + ((wn + ib * 16) >> 1) + b_l_n) * 4;
                ldsm_x4_t(bh[kk][ib], sb + B_OFF + w);
            }
        }
        #pragma unroll
        for (int kk = 0; kk < 2; kk++)
            #pragma unroll
            for (int im = 0; im < 2; im++)
                #pragma unroll
                for (int ib = 0; ib < 2; ib++) {
                    mma_f16(d[im][ib * 2 + 0], ah[kk][im], bh[kk][ib].x, bh[kk][ib].z);
                    mma_f16(d[im][ib * 2 + 1], ah[kk][im], bh[kk][ib].y, bh[kk][ib].w);
                }

        if (i + NSTAGE - 1 < nK) issue((i + NSTAGE - 1) % NSTAGE, i + NSTAGE - 1);
        asm volatile("cp.async.commit_group;" ::: "memory");
    }

    const int g  = lane >> 2;
    const int t2 = (lane & 3) << 1;
    #pragma unroll
    for (int im = 0; im < 2; im++) {
        const int row0 = wm + im * 16 + g;
        #pragma unroll
        for (int j = 0; j < 4; j++) {
            const int col = blockCol + wn + j * 8 + t2;
            float4 v = d[im][j];
            if (bias != nullptr) {
                float b0 = bias[col], b1 = bias[col + 1];
                v.x += b0; v.y += b1; v.z += b0; v.w += b1;
            }
            if (!OUT_HALF) {
                float* C = (float*)Cv;
                *(float2*)&C[(size_t)row0 * ldc + col]       = make_float2(v.x, v.y);
                *(float2*)&C[(size_t)(row0 + 8) * ldc + col] = make_float2(v.z, v.w);
            } else {
                __half* C = (__half*)Cv;
                *(__half2*)&C[(size_t)row0 * ldc + col]       = __floats2half2_rn(v.x, v.y);
                *(__half2*)&C[(size_t)(row0 + 8) * ldc + col] = __floats2half2_rn(v.z, v.w);
            }
        }
    }
}

__global__ __launch_bounds__(256, 2) void qkv_gemm()
{
    extern __shared__ unsigned sm[];
    const unsigned smbase = (unsigned)__cvta_generic_to_shared(sm);
    const int gy = blockIdx.y;
    const __half *A, *Bm; __half *C; int ldb, ldc;
    if (gy < 128) {
        A = g_x16 + (size_t)gy * 128 * GK;
        Bm = g_wq16; ldb = 512;
        C = g_q16 + (size_t)gy * 128 * 512; ldc = 512;
    } else if (gy < 192) {
        const int r = gy - 128;
        A = g_c16 + (size_t)r * 128 * GK;
        Bm = g_wkv16; ldb = 1024;
        C = g_kv16 + (size_t)r * 128 * 1024; ldc = 1024;
    } else {
        const int r = gy - 192;
        A = g_c16 + (size_t)r * 128 * GK;
        Bm = g_wkv16 + 512; ldb = 1024;
        C = g_kv16 + (size_t)r * 128 * 1024 + 512; ldc = 1024;
    }
    gemm_tile<true>(A, Bm, C, ldb, ldc, nullptr, blockIdx.x * 64, smbase);
}

__global__ __launch_bounds__(256, 2) void out_gemm(
    float* __restrict__ out, const float* __restrict__ bias)
{
    extern __shared__ unsigned sm[];
    const unsigned smbase = (unsigned)__cvta_generic_to_shared(sm);
    const __half* A = g_at16 + (size_t)blockIdx.y * 128 * GK;
    float* C = out + (size_t)blockIdx.y * 128 * 512;
    gemm_tile<false>(A, g_wo16, C, 512, 512, bias, blockIdx.x * 64, smbase);
}

// ---------------------------------------------------------------------------
// Sparse neighbor attention. V-phase addresses/weights staged in smem so the
// 32 V loads have no shuffle dependency -> MLP ~8 instead of ~1.
// Accumulation order over j unchanged (numerics identical to R9).
// ---------------------------------------------------------------------------
__global__ __launch_bounds__(256) void attn_kernel(
    const int* __restrict__ idx, const float* __restrict__ bias)
{
    const int bq   = blockIdx.x;
    const int b    = bq >> 13;
    const int h    = threadIdx.x >> 5;
    const int lane = threadIdx.x & 31;

    __shared__ float qs[INNER_];
    __shared__ int   rows_s[KN_];
    __shared__ float ps[HEADS_][KN_];

    const __half2* qsrc = (const __half2*)(g_q16 + (size_t)bq * INNER_);
    #pragma unroll
    for (int i = threadIdx.x; i < INNER_ / 2; i += 256) {
        float2 f = __half22float2(qsrc[i]);
        qs[i * 2] = f.x; qs[i * 2 + 1] = f.y;
    }
    __syncthreads();

    const int   row = b * L_ + (idx[(size_t)bq * KN_ + lane] & (L_ - 1));
    const float bj  = bias[(size_t)bq * KN_ + lane];

    const uint4* kp = (const uint4*)(g_kv16 + (size_t)row * (2 * INNER_) + h * DH_);
    float sim = 0.f;
    #pragma unroll
    for (int t = 0; t < 8; t++) {
        uint4 u = kp[t];
        float2 f0 = __half22float2(*(__half2*)&u.x);
        float2 f1 = __half22float2(*(__half2*)&u.y);
        float2 f2 = __half22float2(*(__half2*)&u.z);
        float2 f3 = __half22float2(*(__half2*)&u.w);
        const float* q8 = qs + h * DH_ + t * 8;
        sim = fmaf(q8[0], f0.x, sim); sim = fmaf(q8[1], f0.y, sim);
        sim = fmaf(q8[2], f1.x, sim); sim = fmaf(q8[3], f1.y, sim);
        sim = fmaf(q8[4], f2.x, sim); sim = fmaf(q8[5], f2.y, sim);
        sim = fmaf(q8[6], f3.x, sim); sim = fmaf(q8[7], f3.y, sim);
    }
    sim = sim * 0.125f + bj;

    float m = sim;
    #pragma unroll
    for (int o = 16; o; o >>= 1) m = fmaxf(m, __shfl_xor_sync(0xffffffffu, m, o));
    float e = __expf(sim - m);
    float s = e;
    #pragma unroll
    for (int o = 16; o; o >>= 1) s += __shfl_xor_sync(0xffffffffu, s, o);
    const float p = e / s;

    // stage rows (identical across warps; warp 0 writes) and per-head p
    if (h == 0) rows_s[lane] = row;
    ps[h][lane] = p;
    __syncthreads();

    // V phase: batches of 8 independent loads, FMAs in original j order
    float2 acc = make_float2(0.f, 0.f);
    const int off = INNER_ + h * DH_ + lane * 2;
    #pragma unroll
    for (int jb = 0; jb < KN_; jb += 8) {
        float2 v2[8];
        #pragma unroll
        for (int u = 0; u < 8; u++) {
            const int rj = rows_s[jb + u];
            v2[u] = __half22float2(
                *(const __half2*)(g_kv16 + (size_t)rj * (2 * INNER_) + off));
        }
        #pragma unroll
        for (int u = 0; u < 8; u++) {
            const float pj = ps[h][jb + u];
            acc.x = fmaf(pj, v2[u].x, acc.x);
            acc.y = fmaf(pj, v2[u].y, acc.y);
        }
    }
    *(__half2*)(g_at16 + (size_t)bq * INNER_ + h * DH_ + lane * 2) =
        __floats2half2_rn(acc.x, acc.y);
}

// ---------------------------------------------------------------------------
extern "C" void kernel_launch(void* const* d_in, const int* in_sizes, int n_in,
                              void* d_out, int out_size)
{
    const float* x       = (const float*)d_in[0];
    const float* context = (const float*)d_in[1];
    const int*   idx     = (const int*)d_in[2];
    const float* bias    = (const float*)d_in[3];
    const float* Wq      = (const float*)d_in[4];
    const float* Wkv     = (const float*)d_in[5];
    const float* Wo      = (const float*)d_in[6];
    const float* bo      = (const float*)d_in[7];
    float*       out     = (float*)d_out;

    cudaFuncSetAttribute(qkv_gemm,
        cudaFuncAttributeMaxDynamicSharedMemorySize, SMEM_BYTES);
    cudaFuncSetAttribute(out_gemm,
        cudaFuncAttributeMaxDynamicSharedMemorySize, SMEM_BYTES);

    convert_all<<<(CVT_C4 + 255) / 256, 256>>>(
        (const float4*)x, (const float4*)context,
        (const float4*)Wq, (const float4*)Wkv, (const float4*)Wo);

    qkv_gemm<<<dim3(8, 256), 256, SMEM_BYTES>>>();

    attn_kernel<<<MQ, 256>>>(idx, bias);

    out_gemm<<<dim3(8, MQ / 128), 256, SMEM_BYTES>>>(out, bo);
}

// round 12
// speedup vs baseline: 2.3012x; 1.3436x over previous
#include <cuda_runtime.h>
#include <cuda_fp16.h>

#define B_ 2
#define HW_ 8192
#define D_ 512
#define L_ 4096
#define KN_ 32
#define HEADS_ 8
#define DH_ 64
#define INNER_ 512
#define MQ (B_ * HW_)   /* 16384 */
#define MC (B_ * L_)    /* 8192  */
#define GK 512          /* K of every GEMM */

// ---------------- device-global scratch (no cudaMalloc allowed) -------------
__device__ __half g_x16[MQ * D_];
__device__ __half g_c16[MC * D_];
__device__ __half g_wq16[D_ * INNER_];
__device__ __half g_wkv16[D_ * 2 * INNER_];
__device__ __half g_wo16[INNER_ * D_];
__device__ __half g_q16[MQ * INNER_];
__device__ __half g_kv16[MC * 2 * INNER_];
__device__ __half g_at16[MQ * INNER_];

// ---------------- helpers ----------------------------------------------------
__device__ __forceinline__ void ldsm_x4(uint4 &r, unsigned addr) {
    asm volatile("ldmatrix.sync.aligned.m8n8.x4.shared.b16 {%0,%1,%2,%3}, [%4];"
        : "=r"(r.x), "=r"(r.y), "=r"(r.z), "=r"(r.w) : "r"(addr));
}
__device__ __forceinline__ void ldsm_x4_t(uint4 &r, unsigned addr) {
    asm volatile("ldmatrix.sync.aligned.m8n8.x4.trans.shared.b16 {%0,%1,%2,%3}, [%4];"
        : "=r"(r.x), "=r"(r.y), "=r"(r.z), "=r"(r.w) : "r"(addr));
}
__device__ __forceinline__ void mma_f16(float4 &d, const uint4 &a,
                                        unsigned b0, unsigned b1) {
    asm("mma.sync.aligned.m16n8k16.row.col.f32.f16.f16.f32 "
        "{%0,%1,%2,%3}, {%4,%5,%6,%7}, {%8,%9}, {%0,%1,%2,%3};"
        : "+f"(d.x), "+f"(d.y), "+f"(d.z), "+f"(d.w)
        : "r"(a.x), "r"(a.y), "r"(a.z), "r"(a.w), "r"(b0), "r"(b1));
}
__device__ __forceinline__ void cp16(unsigned saddr, const void* gaddr) {
    asm volatile("cp.async.cg.shared.global [%0], [%1], 16;"
        :: "r"(saddr), "l"(gaddr));
}

// ---------------- merged fp32 -> fp16 convert (single launch) ---------------
#define CVT_C0 (MQ * D_ / 4)
#define CVT_C1 (CVT_C0 + MC * D_ / 4)
#define CVT_C2 (CVT_C1 + D_ * INNER_ / 4)
#define CVT_C3 (CVT_C2 + D_ * 2 * INNER_ / 4)
#define CVT_C4 (CVT_C3 + INNER_ * D_ / 4)

__global__ __launch_bounds__(256) void convert_all(
    const float4* __restrict__ x, const float4* __restrict__ c,
    const float4* __restrict__ wq, const float4* __restrict__ wkv,
    const float4* __restrict__ wo)
{
    int i = blockIdx.x * 256 + threadIdx.x;
    if (i >= CVT_C4) return;
    const float4* s; uint2* d; int off;
    if      (i < CVT_C0) { s = x;   d = (uint2*)g_x16;   off = 0; }
    else if (i < CVT_C1) { s = c;   d = (uint2*)g_c16;   off = CVT_C0; }
    else if (i < CVT_C2) { s = wq;  d = (uint2*)g_wq16;  off = CVT_C1; }
    else if (i < CVT_C3) { s = wkv; d = (uint2*)g_wkv16; off = CVT_C2; }
    else                 { s = wo;  d = (uint2*)g_wo16;  off = CVT_C3; }
    const int j = i - off;
    float4 v = s[j];
    __half2 p0 = __floats2half2_rn(v.x, v.y);
    __half2 p1 = __floats2half2_rn(v.z, v.w);
    uint2 o;
    o.x = *(unsigned*)&p0;
    o.y = *(unsigned*)&p1;
    d[j] = o;
}

// ---------------------------------------------------------------------------
// Core fp16 GEMM mainloop (verified R8/R9 layout, unchanged).
// ---------------------------------------------------------------------------
#define AW 20
#define BW2 36
#define B_OFF 10240
#define STG_BYTES 14848
#define NSTAGE 5
#define SMEM_BYTES (NSTAGE * STG_BYTES)

template <bool OUT_HALF>
__device__ __forceinline__ void gemm_tile(
    const __half* __restrict__ A, const __half* __restrict__ Bm,
    void* __restrict__ Cv, int ldb, int ldc,
    const float* __restrict__ bias, int blockCol, unsigned smbase)
{
    const int tid  = threadIdx.x;
    const int lane = tid & 31;
    const int warp = tid >> 5;
    const int wm   = (warp >> 1) * 32;
    const int wn   = (warp & 1) * 32;
    const int K = GK;

    const int ar = tid >> 1, ac = (tid & 1) * 2;
    const int bk = tid >> 3, bc = tid & 7;
    const __half* gA = A + (size_t)ar * K + ac * 8;
    const __half* gB = Bm + (size_t)bk * ldb + blockCol + bc * 8;
    const unsigned a_sb = ar * 80 + ac * 16;
    const unsigned b_sb = bk * 144 + bc * 16;

    const int a_l_row = lane & 15;
    const int a_l_k   = (lane >> 4) << 2;
    const int b_l_k   = (lane & 7) + ((lane >> 4) << 3);
    const int b_l_n   = ((lane >> 3) & 1) << 2;

    float4 d[2][4];
    #pragma unroll
    for (int i = 0; i < 2; i++)
        #pragma unroll
        for (int j = 0; j < 4; j++) d[i][j] = make_float4(0.f, 0.f, 0.f, 0.f);

    auto issue = [&](int stage, int chunk) {
        unsigned s = smbase + stage * STG_BYTES;
        const int k0 = chunk * 32;
        cp16(s + a_sb,          gA + k0);
        cp16(s + a_sb + 16,     gA + k0 + 8);
        cp16(s + B_OFF + b_sb,  gB + (size_t)k0 * ldb);
    };

    const int nK = K >> 5;
    #pragma unroll
    for (int c = 0; c < NSTAGE - 1; c++) {
        issue(c, c);
        asm volatile("cp.async.commit_group;" ::: "memory");
    }

    for (int i = 0; i < nK; i++) {
        const int stage = i % NSTAGE;
        asm volatile("cp.async.wait_group %0;" :: "n"(NSTAGE - 2) : "memory");
        __syncthreads();

        const unsigned sb = smbase + stage * STG_BYTES;
        uint4 ah[2][2], bh[2][2];
        #pragma unroll
        for (int kk = 0; kk < 2; kk++) {
            #pragma unroll
            for (int im = 0; im < 2; im++) {
                unsigned w = ((wm + im * 16 + a_l_row) * AW + kk * 8 + a_l_k) * 4;
                ldsm_x4(ah[kk][im], sb + w);
            }
            #pragma unroll
            for (int ib = 0; ib < 2; ib++) {
                unsigned w = ((kk * 16 + b_l_k) * BW2 + ((wn + ib * 16) >> 1) + b_l_n) * 4;
                ldsm_x4_t(bh[kk][ib], sb + B_OFF + w);
            }
        }
        #pragma unroll
        for (int kk = 0; kk < 2; kk++)
            #pragma unroll
            for (int im = 0; im < 2; im++)
                #pragma unroll
                for (int ib = 0; ib < 2; ib++) {
                    mma_f16(d[im][ib * 2 + 0], ah[kk][im], bh[kk][ib].x, bh[kk][ib].z);
                    mma_f16(d[im][ib * 2 + 1], ah[kk][im], bh[kk][ib].y, bh[kk][ib].w);
                }

        if (i + NSTAGE - 1 < nK) issue((i + NSTAGE - 1) % NSTAGE, i + NSTAGE - 1);
        asm volatile("cp.async.commit_group;" ::: "memory");
    }

    const int g  = lane >> 2;
    const int t2 = (lane & 3) << 1;
    #pragma unroll
    for (int im = 0; im < 2; im++) {
        const int row0 = wm + im * 16 + g;
        #pragma unroll
        for (int j = 0; j < 4; j++) {
            const int col = blockCol + wn + j * 8 + t2;
            float4 v = d[im][j];
            if (bias != nullptr) {
                float b0 = bias[col], b1 = bias[col + 1];
                v.x += b0; v.y += b1; v.z += b0; v.w += b1;
            }
            if (!OUT_HALF) {
                float* C = (float*)Cv;
                *(float2*)&C[(size_t)row0 * ldc + col]       = make_float2(v.x, v.y);
                *(float2*)&C[(size_t)(row0 + 8) * ldc + col] = make_float2(v.z, v.w);
            } else {
                __half* C = (__half*)Cv;
                *(__half2*)&C[(size_t)row0 * ldc + col]       = __floats2half2_rn(v.x, v.y);
                *(__half2*)&C[(size_t)(row0 + 8) * ldc + col] = __floats2half2_rn(v.z, v.w);
            }
        }
    }
}

__global__ __launch_bounds__(256, 2) void qkv_gemm()
{
    extern __shared__ unsigned sm[];
    const unsigned smbase = (unsigned)__cvta_generic_to_shared(sm);
    const int gy = blockIdx.y;
    const __half *A, *Bm; __half *C; int ldb, ldc;
    if (gy < 128) {
        A = g_x16 + (size_t)gy * 128 * GK;
        Bm = g_wq16; ldb = 512;
        C = g_q16 + (size_t)gy * 128 * 512; ldc = 512;
    } else if (gy < 192) {
        const int r = gy - 128;
        A = g_c16 + (size_t)r * 128 * GK;
        Bm = g_wkv16; ldb = 1024;
        C = g_kv16 + (size_t)r * 128 * 1024; ldc = 1024;
    } else {
        const int r = gy - 192;
        A = g_c16 + (size_t)r * 128 * GK;
        Bm = g_wkv16 + 512; ldb = 1024;
        C = g_kv16 + (size_t)r * 128 * 1024 + 512; ldc = 1024;
    }
    gemm_tile<true>(A, Bm, C, ldb, ldc, nullptr, blockIdx.x * 64, smbase);
}

__global__ __launch_bounds__(256, 2) void out_gemm(
    float* __restrict__ out, const float* __restrict__ bias)
{
    extern __shared__ unsigned sm[];
    const unsigned smbase = (unsigned)__cvta_generic_to_shared(sm);
    const __half* A = g_at16 + (size_t)blockIdx.y * 128 * GK;
    float* C = out + (size_t)blockIdx.y * 128 * 512;
    gemm_tile<false>(A, g_wo16, C, 512, 512, bias, blockIdx.x * 64, smbase);
}

// ---------------------------------------------------------------------------
// Sparse neighbor attention.
// K phase: 4 lanes cooperate per neighbor row (lane = group g x quarter qd);
// pass p handles neighbor j=8p+g; the 4 lanes' 32B slices sit in ONE 128B
// line (head slice is 128B aligned) -> 8 lines per load instr instead of 32
// (L1 wavefronts / block: ~2048 -> ~512). Group tree-reduce (2 butterflies),
// then 4 shuffles put sim_j into lane j for the softmax.
// V phase: staged rows/probs, batched coalesced loads (verified R10).
// ---------------------------------------------------------------------------
__global__ __launch_bounds__(256) void attn_kernel(
    const int* __restrict__ idx, const float* __restrict__ bias)
{
    const int bq   = blockIdx.x;
    const int b    = bq >> 13;
    const int h    = threadIdx.x >> 5;
    const int lane = threadIdx.x & 31;

    __shared__ float qs[INNER_];
    __shared__ int   rows_s[KN_];
    __shared__ float ps[HEADS_][KN_];

    // stage rows (warp 0) and q (all threads)
    if (threadIdx.x < KN_)
        rows_s[threadIdx.x] =
            b * L_ + (idx[(size_t)bq * KN_ + threadIdx.x] & (L_ - 1));
    const __half2* qsrc = (const __half2*)(g_q16 + (size_t)bq * INNER_);
    #pragma unroll
    for (int i = threadIdx.x; i < INNER_ / 2; i += 256) {
        float2 f = __half22float2(qsrc[i]);
        qs[i * 2] = f.x; qs[i * 2 + 1] = f.y;
    }
    __syncthreads();

    // ---- K phase: cooperative gather ----
    const int g  = lane >> 2;       // neighbor group 0..7
    const int qd = lane & 3;        // quarter 0..3 (16 dims each)
    float pv[4];
    #pragma unroll
    for (int p = 0; p < 4; p++) {
        const int rj = rows_s[p * 8 + g];
        const uint4* kp = (const uint4*)(g_kv16
            + (size_t)rj * (2 * INNER_) + h * DH_ + qd * 16);
        uint4 u0 = kp[0], u1 = kp[1];
        const float* q16p = qs + h * DH_ + qd * 16;
        float t = 0.f;
        {
            float2 f;
            f = __half22float2(*(__half2*)&u0.x); t = fmaf(q16p[0], f.x, t); t = fmaf(q16p[1], f.y, t);
            f = __half22float2(*(__half2*)&u0.y); t = fmaf(q16p[2], f.x, t); t = fmaf(q16p[3], f.y, t);
            f = __half22float2(*(__half2*)&u0.z); t = fmaf(q16p[4], f.x, t); t = fmaf(q16p[5], f.y, t);
            f = __half22float2(*(__half2*)&u0.w); t = fmaf(q16p[6], f.x, t); t = fmaf(q16p[7], f.y, t);
            f = __half22float2(*(__half2*)&u1.x); t = fmaf(q16p[8], f.x, t); t = fmaf(q16p[9], f.y, t);
            f = __half22float2(*(__half2*)&u1.y); t = fmaf(q16p[10], f.x, t); t = fmaf(q16p[11], f.y, t);
            f = __half22float2(*(__half2*)&u1.z); t = fmaf(q16p[12], f.x, t); t = fmaf(q16p[13], f.y, t);
            f = __half22float2(*(__half2*)&u1.w); t = fmaf(q16p[14], f.x, t); t = fmaf(q16p[15], f.y, t);
        }
        t += __shfl_xor_sync(0xffffffffu, t, 1);
        t += __shfl_xor_sync(0xffffffffu, t, 2);
        pv[p] = t;     // all 4 lanes of group g hold sim_{8p+g}
    }
    // redistribute: lane l wants sim_l = pv[l>>3] from lane 4*(l&7)
    const int src = (lane & 7) << 2;
    const float t0 = __shfl_sync(0xffffffffu, pv[0], src);
    const float t1 = __shfl_sync(0xffffffffu, pv[1], src);
    const float t2 = __shfl_sync(0xffffffffu, pv[2], src);
    const float t3 = __shfl_sync(0xffffffffu, pv[3], src);
    const int pselect = lane >> 3;
    float dot = (pselect == 0) ? t0 : (pselect == 1) ? t1 : (pselect == 2) ? t2 : t3;

    const float bj  = bias[(size_t)bq * KN_ + lane];
    float sim = dot * 0.125f + bj;

    // ---- softmax over 32 neighbors (lane j holds sim_j) ----
    float m = sim;
    #pragma unroll
    for (int o = 16; o; o >>= 1) m = fmaxf(m, __shfl_xor_sync(0xffffffffu, m, o));
    float e = __expf(sim - m);
    float s = e;
    #pragma unroll
    for (int o = 16; o; o >>= 1) s += __shfl_xor_sync(0xffffffffu, s, o);
    const float p = e / s;

    ps[h][lane] = p;
    __syncthreads();

    // ---- V phase: batched coalesced loads ----
    float2 acc = make_float2(0.f, 0.f);
    const int off = INNER_ + h * DH_ + lane * 2;
    #pragma unroll
    for (int jb = 0; jb < KN_; jb += 8) {
        float2 v2[8];
        #pragma unroll
        for (int u = 0; u < 8; u++) {
            const int rj = rows_s[jb + u];
            v2[u] = __half22float2(
                *(const __half2*)(g_kv16 + (size_t)rj * (2 * INNER_) + off));
        }
        #pragma unroll
        for (int u = 0; u < 8; u++) {
            const float pj = ps[h][jb + u];
            acc.x = fmaf(pj, v2[u].x, acc.x);
            acc.y = fmaf(pj, v2[u].y, acc.y);
        }
    }
    *(__half2*)(g_at16 + (size_t)bq * INNER_ + h * DH_ + lane * 2) =
        __floats2half2_rn(acc.x, acc.y);
}

// ---------------------------------------------------------------------------
extern "C" void kernel_launch(void* const* d_in, const int* in_sizes, int n_in,
                              void* d_out, int out_size)
{
    const float* x       = (const float*)d_in[0];
    const float* context = (const float*)d_in[1];
    const int*   idx     = (const int*)d_in[2];
    const float* bias    = (const float*)d_in[3];
    const float* Wq      = (const float*)d_in[4];
    const float* Wkv     = (const float*)d_in[5];
    const float* Wo      = (const float*)d_in[6];
    const float* bo      = (const float*)d_in[7];
    float*       out     = (float*)d_out;

    cudaFuncSetAttribute(qkv_gemm,
        cudaFuncAttributeMaxDynamicSharedMemorySize, SMEM_BYTES);
    cudaFuncSetAttribute(out_gemm,
        cudaFuncAttributeMaxDynamicSharedMemorySize, SMEM_BYTES);

    convert_all<<<(CVT_C4 + 255) / 256, 256>>>(
        (const float4*)x, (const float4*)context,
        (const float4*)Wq, (const float4*)Wkv, (const float4*)Wo);

    qkv_gemm<<<dim3(8, 256), 256, SMEM_BYTES>>>();

    attn_kernel<<<MQ, 256>>>(idx, bias);

    out_gemm<<<dim3(8, MQ / 128), 256, SMEM_BYTES>>>(out, bo);
}

// round 13
// speedup vs baseline: 2.5148x; 1.0928x over previous
#include <cuda_runtime.h>
#include <cuda_fp16.h>

#define B_ 2
#define HW_ 8192
#define D_ 512
#define L_ 4096
#define KN_ 32
#define HEADS_ 8
#define DH_ 64
#define INNER_ 512
#define MQ (B_ * HW_)   /* 16384 */
#define MC (B_ * L_)    /* 8192  */
#define GK 512          /* K of every GEMM */

// ---------------- device-global scratch (no cudaMalloc allowed) -------------
__device__ __half g_x16[MQ * D_];
__device__ __half g_c16[MC * D_];
__device__ __half g_wq16[D_ * INNER_];
__device__ __half g_wkv16[D_ * 2 * INNER_];
__device__ __half g_wo16[INNER_ * D_];
__device__ __half g_q16[MQ * INNER_];
__device__ __half g_kv16[MC * 2 * INNER_];
__device__ __half g_at16[MQ * INNER_];

// ---------------- helpers ----------------------------------------------------
__device__ __forceinline__ void ldsm_x4(uint4 &r, unsigned addr) {
    asm volatile("ldmatrix.sync.aligned.m8n8.x4.shared.b16 {%0,%1,%2,%3}, [%4];"
        : "=r"(r.x), "=r"(r.y), "=r"(r.z), "=r"(r.w) : "r"(addr));
}
__device__ __forceinline__ void ldsm_x4_t(uint4 &r, unsigned addr) {
    asm volatile("ldmatrix.sync.aligned.m8n8.x4.trans.shared.b16 {%0,%1,%2,%3}, [%4];"
        : "=r"(r.x), "=r"(r.y), "=r"(r.z), "=r"(r.w) : "r"(addr));
}
__device__ __forceinline__ void mma_f16(float4 &d, const uint4 &a,
                                        unsigned b0, unsigned b1) {
    asm("mma.sync.aligned.m16n8k16.row.col.f32.f16.f16.f32 "
        "{%0,%1,%2,%3}, {%4,%5,%6,%7}, {%8,%9}, {%0,%1,%2,%3};"
        : "+f"(d.x), "+f"(d.y), "+f"(d.z), "+f"(d.w)
        : "r"(a.x), "r"(a.y), "r"(a.z), "r"(a.w), "r"(b0), "r"(b1));
}
__device__ __forceinline__ void cp16(unsigned saddr, const void* gaddr) {
    asm volatile("cp.async.cg.shared.global [%0], [%1], 16;"
        :: "r"(saddr), "l"(gaddr));
}

// ---------------- merged fp32 -> fp16 convert (single launch) ---------------
#define CVT_C0 (MQ * D_ / 4)
#define CVT_C1 (CVT_C0 + MC * D_ / 4)
#define CVT_C2 (CVT_C1 + D_ * INNER_ / 4)
#define CVT_C3 (CVT_C2 + D_ * 2 * INNER_ / 4)
#define CVT_C4 (CVT_C3 + INNER_ * D_ / 4)

__global__ __launch_bounds__(256) void convert_all(
    const float4* __restrict__ x, const float4* __restrict__ c,
    const float4* __restrict__ wq, const float4* __restrict__ wkv,
    const float4* __restrict__ wo)
{
    int i = blockIdx.x * 256 + threadIdx.x;
    if (i >= CVT_C4) return;
    const float4* s; uint2* d; int off;
    if      (i < CVT_C0) { s = x;   d = (uint2*)g_x16;   off = 0; }
    else if (i < CVT_C1) { s = c;   d = (uint2*)g_c16;   off = CVT_C0; }
    else if (i < CVT_C2) { s = wq;  d = (uint2*)g_wq16;  off = CVT_C1; }
    else if (i < CVT_C3) { s = wkv; d = (uint2*)g_wkv16; off = CVT_C2; }
    else                 { s = wo;  d = (uint2*)g_wo16;  off = CVT_C3; }
    const int j = i - off;
    float4 v = s[j];
    __half2 p0 = __floats2half2_rn(v.x, v.y);
    __half2 p1 = __floats2half2_rn(v.z, v.w);
    uint2 o;
    o.x = *(unsigned*)&p0;
    o.y = *(unsigned*)&p1;
    d[j] = o;
}

// ---------------------------------------------------------------------------
// fp16 GEMM: block tile 128x128xK32, 256 threads = 8 warps (4x2, warp tile
// 32x64), 2 CTAs/SM, 4-stage cp.async. A smem [m][k] stride 20 words
// (verified); B smem [k][n] stride 68 words (R3-verified 128-wide layout,
// conflict-free ldmatrix.trans).
// ---------------------------------------------------------------------------
#define AW 20
#define BW 68
#define B_OFF 10240             /* A: 128*20w*4B */
#define STG_BYTES 18944         /* + B: 32*68w*4B = 8704 */
#define NSTAGE 4
#define SMEM_BYTES (NSTAGE * STG_BYTES)

template <bool OUT_HALF>
__device__ __forceinline__ void gemm_tile(
    const __half* __restrict__ A, const __half* __restrict__ Bm,
    void* __restrict__ Cv, int ldb, int ldc,
    const float* __restrict__ bias, int blockCol, unsigned smbase)
{
    const int tid  = threadIdx.x;
    const int lane = tid & 31;
    const int warp = tid >> 5;
    const int wm   = (warp >> 1) * 32;   // 4 warps down M (128)
    const int wn   = (warp & 1) * 64;    // 2 warps across N (128)
    const int K = GK;

    // loaders: A 128 rows x 4 chunks (2/thread: rows r, r+64);
    //          B 32 rows x 16 chunks (2/thread: rows r, r+16)
    const int ar = tid >> 2, ac = tid & 3;
    const int bk = tid >> 4, bc = tid & 15;
    const __half* gA = A + (size_t)ar * K + ac * 8;
    const __half* gB = Bm + (size_t)bk * ldb + blockCol + bc * 8;
    const unsigned a_sb = ar * 80 + ac * 16;
    const unsigned b_sb = bk * 272 + bc * 16;

    // ldmatrix lane maps (A verified R6-R11, B verified R3/R4 with BW=68)
    const int a_l_row = lane & 15;
    const int a_l_k   = (lane >> 4) << 2;
    const int b_l_k   = (lane & 7) + ((lane >> 4) << 3);
    const int b_l_n   = ((lane >> 3) & 1) << 2;

    float4 d[2][8];
    #pragma unroll
    for (int i = 0; i < 2; i++)
        #pragma unroll
        for (int j = 0; j < 8; j++) d[i][j] = make_float4(0.f, 0.f, 0.f, 0.f);

    auto issue = [&](int stage, int chunk) {
        unsigned s = smbase + stage * STG_BYTES;
        const int k0 = chunk * 32;
        cp16(s + a_sb,                  gA + k0);
        cp16(s + a_sb + 64 * 80,        gA + k0 + (size_t)64 * K);
        cp16(s + B_OFF + b_sb,          gB + (size_t)k0 * ldb);
        cp16(s + B_OFF + b_sb + 16 * 272, gB + (size_t)(k0 + 16) * ldb);
    };

    const int nK = K >> 5;
    #pragma unroll
    for (int c = 0; c < NSTAGE - 1; c++) {
        issue(c, c);
        asm volatile("cp.async.commit_group;" ::: "memory");
    }

    for (int i = 0; i < nK; i++) {
        const int stage = i % NSTAGE;
        asm volatile("cp.async.wait_group %0;" :: "n"(NSTAGE - 2) : "memory");
        __syncthreads();

        const unsigned sb = smbase + stage * STG_BYTES;
        #pragma unroll
        for (int kk = 0; kk < 2; kk++) {
            uint4 ah[2], bh[4];
            #pragma unroll
            for (int im = 0; im < 2; im++) {
                unsigned w = ((wm + im * 16 + a_l_row) * AW + kk * 8 + a_l_k) * 4;
                ldsm_x4(ah[im], sb + w);
            }
            #pragma unroll
            for (int ib = 0; ib < 4; ib++) {
                unsigned w = ((kk * 16 + b_l_k) * BW + ((wn + ib * 16) >> 1) + b_l_n) * 4;
                ldsm_x4_t(bh[ib], sb + B_OFF + w);
            }
            #pragma unroll
            for (int im = 0; im < 2; im++)
                #pragma unroll
                for (int ib = 0; ib < 4; ib++) {
                    mma_f16(d[im][ib * 2 + 0], ah[im], bh[ib].x, bh[ib].z);
                    mma_f16(d[im][ib * 2 + 1], ah[im], bh[ib].y, bh[ib].w);
                }
        }

        if (i + NSTAGE - 1 < nK) issue((i + NSTAGE - 1) % NSTAGE, i + NSTAGE - 1);
        asm volatile("cp.async.commit_group;" ::: "memory");
    }

    const int g  = lane >> 2;
    const int t2 = (lane & 3) << 1;
    #pragma unroll
    for (int im = 0; im < 2; im++) {
        const int row0 = wm + im * 16 + g;
        #pragma unroll
        for (int j = 0; j < 8; j++) {
            const int col = blockCol + wn + j * 8 + t2;
            float4 v = d[im][j];
            if (bias != nullptr) {
                float b0 = bias[col], b1 = bias[col + 1];
                v.x += b0; v.y += b1; v.z += b0; v.w += b1;
            }
            if (!OUT_HALF) {
                float* C = (float*)Cv;
                *(float2*)&C[(size_t)row0 * ldc + col]       = make_float2(v.x, v.y);
                *(float2*)&C[(size_t)(row0 + 8) * ldc + col] = make_float2(v.z, v.w);
            } else {
                __half* C = (__half*)Cv;
                *(__half2*)&C[(size_t)row0 * ldc + col]       = __floats2half2_rn(v.x, v.y);
                *(__half2*)&C[(size_t)(row0 + 8) * ldc + col] = __floats2half2_rn(v.z, v.w);
            }
        }
    }
}

__global__ __launch_bounds__(256, 2) void qkv_gemm()
{
    extern __shared__ unsigned sm[];
    const unsigned smbase = (unsigned)__cvta_generic_to_shared(sm);
    const int gy = blockIdx.y;
    const __half *A, *Bm; __half *C; int ldb, ldc;
    if (gy < 128) {
        A = g_x16 + (size_t)gy * 128 * GK;
        Bm = g_wq16; ldb = 512;
        C = g_q16 + (size_t)gy * 128 * 512; ldc = 512;
    } else if (gy < 192) {
        const int r = gy - 128;
        A = g_c16 + (size_t)r * 128 * GK;
        Bm = g_wkv16; ldb = 1024;
        C = g_kv16 + (size_t)r * 128 * 1024; ldc = 1024;
    } else {
        const int r = gy - 192;
        A = g_c16 + (size_t)r * 128 * GK;
        Bm = g_wkv16 + 512; ldb = 1024;
        C = g_kv16 + (size_t)r * 128 * 1024 + 512; ldc = 1024;
    }
    gemm_tile<true>(A, Bm, C, ldb, ldc, nullptr, blockIdx.x * 128, smbase);
}

__global__ __launch_bounds__(256, 2) void out_gemm(
    float* __restrict__ out, const float* __restrict__ bias)
{
    extern __shared__ unsigned sm[];
    const unsigned smbase = (unsigned)__cvta_generic_to_shared(sm);
    const __half* A = g_at16 + (size_t)blockIdx.y * 128 * GK;
    float* C = out + (size_t)blockIdx.y * 128 * 512;
    gemm_tile<false>(A, g_wo16, C, 512, 512, bias, blockIdx.x * 128, smbase);
}

// ---------------------------------------------------------------------------
// Sparse neighbor attention (verified R11: cooperative K gather + batched V).
// ---------------------------------------------------------------------------
__global__ __launch_bounds__(256) void attn_kernel(
    const int* __restrict__ idx, const float* __restrict__ bias)
{
    const int bq   = blockIdx.x;
    const int b    = bq >> 13;
    const int h    = threadIdx.x >> 5;
    const int lane = threadIdx.x & 31;

    __shared__ float qs[INNER_];
    __shared__ int   rows_s[KN_];
    __shared__ float ps[HEADS_][KN_];

    if (threadIdx.x < KN_)
        rows_s[threadIdx.x] =
            b * L_ + (idx[(size_t)bq * KN_ + threadIdx.x] & (L_ - 1));
    const __half2* qsrc = (const __half2*)(g_q16 + (size_t)bq * INNER_);
    #pragma unroll
    for (int i = threadIdx.x; i < INNER_ / 2; i += 256) {
        float2 f = __half22float2(qsrc[i]);
        qs[i * 2] = f.x; qs[i * 2 + 1] = f.y;
    }
    __syncthreads();

    const int g  = lane >> 2;
    const int qd = lane & 3;
    float pv[4];
    #pragma unroll
    for (int p = 0; p < 4; p++) {
        const int rj = rows_s[p * 8 + g];
        const uint4* kp = (const uint4*)(g_kv16
            + (size_t)rj * (2 * INNER_) + h * DH_ + qd * 16);
        uint4 u0 = kp[0], u1 = kp[1];
        const float* q16p = qs + h * DH_ + qd * 16;
        float t = 0.f;
        {
            float2 f;
            f = __half22float2(*(__half2*)&u0.x); t = fmaf(q16p[0], f.x, t); t = fmaf(q16p[1], f.y, t);
            f = __half22float2(*(__half2*)&u0.y); t = fmaf(q16p[2], f.x, t); t = fmaf(q16p[3], f.y, t);
            f = __half22float2(*(__half2*)&u0.z); t = fmaf(q16p[4], f.x, t); t = fmaf(q16p[5], f.y, t);
            f = __half22float2(*(__half2*)&u0.w); t = fmaf(q16p[6], f.x, t); t = fmaf(q16p[7], f.y, t);
            f = __half22float2(*(__half2*)&u1.x); t = fmaf(q16p[8], f.x, t); t = fmaf(q16p[9], f.y, t);
            f = __half22float2(*(__half2*)&u1.y); t = fmaf(q16p[10], f.x, t); t = fmaf(q16p[11], f.y, t);
            f = __half22float2(*(__half2*)&u1.z); t = fmaf(q16p[12], f.x, t); t = fmaf(q16p[13], f.y, t);
            f = __half22float2(*(__half2*)&u1.w); t = fmaf(q16p[14], f.x, t); t = fmaf(q16p[15], f.y, t);
        }
        t += __shfl_xor_sync(0xffffffffu, t, 1);
        t += __shfl_xor_sync(0xffffffffu, t, 2);
        pv[p] = t;
    }
    const int src = (lane & 7) << 2;
    const float t0 = __shfl_sync(0xffffffffu, pv[0], src);
    const float t1 = __shfl_sync(0xffffffffu, pv[1], src);
    const float t2 = __shfl_sync(0xffffffffu, pv[2], src);
    const float t3 = __shfl_sync(0xffffffffu, pv[3], src);
    const int pselect = lane >> 3;
    float dot = (pselect == 0) ? t0 : (pselect == 1) ? t1 : (pselect == 2) ? t2 : t3;

    const float bj  = bias[(size_t)bq * KN_ + lane];
    float sim = dot * 0.125f + bj;

    float m = sim;
    #pragma unroll
    for (int o = 16; o; o >>= 1) m = fmaxf(m, __shfl_xor_sync(0xffffffffu, m, o));
    float e = __expf(sim - m);
    float s = e;
    #pragma unroll
    for (int o = 16; o; o >>= 1) s += __shfl_xor_sync(0xffffffffu, s, o);
    const float p = e / s;

    ps[h][lane] = p;
    __syncthreads();

    float2 acc = make_float2(0.f, 0.f);
    const int off = INNER_ + h * DH_ + lane * 2;
    #pragma unroll
    for (int jb = 0; jb < KN_; jb += 8) {
        float2 v2[8];
        #pragma unroll
        for (int u = 0; u < 8; u++) {
            const int rj = rows_s[jb + u];
            v2[u] = __half22float2(
                *(const __half2*)(g_kv16 + (size_t)rj * (2 * INNER_) + off));
        }
        #pragma unroll
        for (int u = 0; u < 8; u++) {
            const float pj = ps[h][jb + u];
            acc.x = fmaf(pj, v2[u].x, acc.x);
            acc.y = fmaf(pj, v2[u].y, acc.y);
        }
    }
    *(__half2*)(g_at16 + (size_t)bq * INNER_ + h * DH_ + lane * 2) =
        __floats2half2_rn(acc.x, acc.y);
}

// ---------------------------------------------------------------------------
extern "C" void kernel_launch(void* const* d_in, const int* in_sizes, int n_in,
                              void* d_out, int out_size)
{
    const float* x       = (const float*)d_in[0];
    const float* context = (const float*)d_in[1];
    const int*   idx     = (const int*)d_in[2];
    const float* bias    = (const float*)d_in[3];
    const float* Wq      = (const float*)d_in[4];
    const float* Wkv     = (const float*)d_in[5];
    const float* Wo      = (const float*)d_in[6];
    const float* bo      = (const float*)d_in[7];
    float*       out     = (float*)d_out;

    cudaFuncSetAttribute(qkv_gemm,
        cudaFuncAttributeMaxDynamicSharedMemorySize, SMEM_BYTES);
    cudaFuncSetAttribute(out_gemm,
        cudaFuncAttributeMaxDynamicSharedMemorySize, SMEM_BYTES);

    convert_all<<<(CVT_C4 + 255) / 256, 256>>>(
        (const float4*)x, (const float4*)context,
        (const float4*)Wq, (const float4*)Wkv, (const float4*)Wo);

    qkv_gemm<<<dim3(4, 256), 256, SMEM_BYTES>>>();

    attn_kernel<<<MQ, 256>>>(idx, bias);

    out_gemm<<<dim3(4, MQ / 128), 256, SMEM_BYTES>>>(out, bo);
}